// round 3
// baseline (speedup 1.0000x reference)
#include <cuda_runtime.h>
#include <math.h>

#define BB 128
#define TT 512
#define ENC 512
#define HHD 512
#define AA 18
#define MM (BB*TT)
#define G4 (4*HHD)

#define N_LOGITS ((size_t)MM*AA)
#define OFF_LOGITS ((size_t)0)
#define OFF_VALUES (N_LOGITS)
#define OFF_HT (OFF_VALUES + (size_t)MM)
#define OFF_CT (OFF_HT + (size_t)BB*HHD)
#define OFF_AR (OFF_CT + (size_t)BB*HHD)
#define OFF_TAR (OFF_AR + 1)
#define NGATE ((size_t)MM*HHD)
#define OFF_IG (OFF_TAR + 1)
#define OFF_FG (OFF_IG + NGATE)
#define OFF_GG (OFF_FG + NGATE)
#define OFF_OG (OFF_GG + NGATE)

__device__ __align__(16) float g_enc1[(size_t)MM*ENC];   // enc1; later reused as LSTM out (B,T,H)
__device__ __align__(16) float g_enc2[(size_t)MM*ENC];
__device__ __align__(16) float g_xg[(size_t)MM*G4];
__device__ __align__(16) float g_h[2][BB*HHD];
#define LOSS_BLOCKS 2048
__device__ double g_part[2][LOSS_BLOCKS];
__device__ unsigned g_arrive;
__device__ unsigned g_release;

__device__ __forceinline__ float sigf(float x){ return 1.f/(1.f+expf(-x)); }
__device__ __forceinline__ unsigned long long f2dup(float x){
    unsigned long long r; asm("mov.b64 %0, {%1, %1};" : "=l"(r) : "r"(__float_as_uint(x))); return r;
}
__device__ __forceinline__ void fma2(unsigned long long& d, unsigned long long a, unsigned long long b){
    asm("fma.rn.f32x2 %0, %1, %2, %0;" : "+l"(d) : "l"(a), "l"(b));
}
__device__ __forceinline__ void unpack2(unsigned long long v, float& lo, float& hi){
    unsigned l,h; asm("mov.b64 {%0, %1}, %2;" : "=r"(l), "=r"(h) : "l"(v));
    lo=__uint_as_float(l); hi=__uint_as_float(h);
}

// GEMM (NT): C[m][n] = act(sum_k A[m][k]*B[n][k] + bias1[n] (+bias2[n]))
// BM=BN=128, BK=16, 256 threads, 8x8 thread tile, f32x2 accum.
template<int ACT>
__global__ __launch_bounds__(256)
void gemm_nt(const float* __restrict__ A, const float* __restrict__ Bm,
             const float* __restrict__ bias1, const float* __restrict__ bias2,
             float* __restrict__ C, int K, int N)
{
    __shared__ __align__(16) float As[16][132];
    __shared__ __align__(16) float Bs[16][132];
    const int tid = threadIdx.x;
    const int tx = tid & 15, ty = tid >> 4;
    const float* Ab = A + (size_t)blockIdx.y * 128 * K;
    const float* Bb = Bm + (size_t)blockIdx.x * 128 * K;

    unsigned long long acc[4][8];
#pragma unroll
    for (int i=0;i<4;i++)
#pragma unroll
        for (int j=0;j<8;j++) acc[i][j]=0ull;

    for (int k0=0;k0<K;k0+=16){
#pragma unroll
        for (int i=0;i<2;i++){
            int l = tid + i*256;
            int row = l>>2, c4 = (l&3)<<2;
            float4 va = *(const float4*)(Ab + (size_t)row*K + k0 + c4);
            As[c4+0][row]=va.x; As[c4+1][row]=va.y; As[c4+2][row]=va.z; As[c4+3][row]=va.w;
            float4 vb = *(const float4*)(Bb + (size_t)row*K + k0 + c4);
            Bs[c4+0][row]=vb.x; Bs[c4+1][row]=vb.y; Bs[c4+2][row]=vb.z; Bs[c4+3][row]=vb.w;
        }
        __syncthreads();
#pragma unroll
        for (int kk=0;kk<16;kk++){
            ulonglong2 ua = *(const ulonglong2*)&As[kk][ty*8];
            ulonglong2 ub = *(const ulonglong2*)&As[kk][ty*8+4];
            unsigned long long a2[4] = { ua.x, ua.y, ub.x, ub.y };
            float4 b0 = *(const float4*)&Bs[kk][tx*8];
            float4 b1 = *(const float4*)&Bs[kk][tx*8+4];
            unsigned long long bd[8] = { f2dup(b0.x),f2dup(b0.y),f2dup(b0.z),f2dup(b0.w),
                                         f2dup(b1.x),f2dup(b1.y),f2dup(b1.z),f2dup(b1.w) };
#pragma unroll
            for (int i=0;i<4;i++)
#pragma unroll
                for (int j=0;j<8;j++) fma2(acc[i][j], a2[i], bd[j]);
        }
        __syncthreads();
    }

    const int colb = blockIdx.x*128 + tx*8;
    float bv[8];
#pragma unroll
    for (int j=0;j<8;j++) bv[j] = bias1[colb+j] + (bias2 ? bias2[colb+j] : 0.f);
    const size_t rowb = (size_t)blockIdx.y*128 + ty*8;
#pragma unroll
    for (int i=0;i<4;i++){
        float v0[8], v1[8];
#pragma unroll
        for (int j=0;j<8;j++){
            float x0,x1; unpack2(acc[i][j],x0,x1);
            x0+=bv[j]; x1+=bv[j];
            if (ACT==1){ x0 = x0/(1.f+expf(-x0)); x1 = x1/(1.f+expf(-x1)); }
            v0[j]=x0; v1[j]=x1;
        }
        float* c0 = C + (rowb + 2*i)*(size_t)N + colb;
        float* c1 = c0 + N;
        *(float4*)(c0)   = make_float4(v0[0],v0[1],v0[2],v0[3]);
        *(float4*)(c0+4) = make_float4(v0[4],v0[5],v0[6],v0[7]);
        *(float4*)(c1)   = make_float4(v1[0],v1[1],v1[2],v1[3]);
        *(float4*)(c1+4) = make_float4(v1[4],v1[5],v1[6],v1[7]);
    }
}

__global__ void init_kernel(const float* __restrict__ hxs)
{
    if (blockIdx.x==0 && threadIdx.x==0){ g_arrive=0u; g_release=0u; }
    size_t i = (size_t)blockIdx.x*256 + threadIdx.x;
    ((float4*)g_h[0])[i] = ((const float4*)hxs)[i];
}

// Persistent LSTM: 128 blocks (8 b-tiles x 16 h-tiles), 256 threads.
// Thread owns 2 (b,h) cells x 4 gates; c in registers; grid barrier per step.
__global__ __launch_bounds__(256)
void lstm_kernel(const float* __restrict__ Whh, const float* __restrict__ cxs,
                 float* __restrict__ dout)
{
    __shared__ __align__(16) float hs[16][516];
    __shared__ __align__(16) float u_buf[5*16*32];
#define XS(r,g,q) u_buf[(((r)*4+(g))*32)+(q)]
#define ST(a,r,q) u_buf[(((a)*16+(r))*32)+(q)]
    const int tid = threadIdx.x;
    const int b0 = (blockIdx.x & 7) * 16;
    const int hbase = (blockIdx.x >> 3) * 32;
    const int hloc = tid >> 3;
    const int bg = tid & 7;
    const int h = hbase + hloc;
    const int rA = bg*2, rB = rA+1;
    const int bA = b0+rA, bB = b0+rB;

    const float* w0 = Whh + (size_t)(0*HHD + h)*HHD;
    const float* w1 = Whh + (size_t)(1*HHD + h)*HHD;
    const float* w2 = Whh + (size_t)(2*HHD + h)*HHD;
    const float* w3 = Whh + (size_t)(3*HHD + h)*HHD;

    float cA = cxs[(size_t)bA*HHD + h];
    float cB = cxs[(size_t)bB*HHD + h];

    float* outb = g_enc1;
    float* gp1 = dout + OFF_IG;  float* gp2 = dout + OFF_FG;
    float* gp3 = dout + OFF_GG;  float* gp4 = dout + OFF_OG;

    for (int t=0;t<TT;t++){
        const float* hin = g_h[t&1];
        float* hnx = g_h[(t+1)&1];

        for (int l=tid;l<2048;l+=256){
            int r=l>>7, c4=(l&127)<<2;
            *(float4*)&hs[r][c4] = *(const float4*)(hin + (size_t)(b0+r)*HHD + c4);
        }
        for (int l=tid;l<512;l+=256){
            int r=l>>5, rem=l&31, g=rem>>3, q4=(rem&7)<<2;
            *(float4*)&XS(r,g,q4) =
                *(const float4*)(g_xg + ((size_t)(b0+r)*TT + t)*G4 + (size_t)g*HHD + hbase + q4);
        }
        __syncthreads();

        float a0=0.f,a1=0.f,a2=0.f,a3=0.f,d0=0.f,d1=0.f,d2=0.f,d3=0.f;
#pragma unroll 2
        for (int k=0;k<HHD;k+=4){
            float4 wa = __ldg((const float4*)(w0+k));
            float4 wb = __ldg((const float4*)(w1+k));
            float4 wc = __ldg((const float4*)(w2+k));
            float4 wd = __ldg((const float4*)(w3+k));
            float4 hA = *(const float4*)&hs[rA][k];
            float4 hB = *(const float4*)&hs[rB][k];
            a0 += hA.x*wa.x + hA.y*wa.y + hA.z*wa.z + hA.w*wa.w;
            a1 += hA.x*wb.x + hA.y*wb.y + hA.z*wb.z + hA.w*wb.w;
            a2 += hA.x*wc.x + hA.y*wc.y + hA.z*wc.z + hA.w*wc.w;
            a3 += hA.x*wd.x + hA.y*wd.y + hA.z*wd.z + hA.w*wd.w;
            d0 += hB.x*wa.x + hB.y*wa.y + hB.z*wa.z + hB.w*wa.w;
            d1 += hB.x*wb.x + hB.y*wb.y + hB.z*wb.z + hB.w*wb.w;
            d2 += hB.x*wc.x + hB.y*wc.y + hB.z*wc.z + hB.w*wc.w;
            d3 += hB.x*wd.x + hB.y*wd.y + hB.z*wd.z + hB.w*wd.w;
        }

        float iA = sigf(a0 + XS(rA,0,hloc));
        float fA = sigf(a1 + XS(rA,1,hloc));
        float gA = tanhf(a2 + XS(rA,2,hloc));
        float oA = sigf(a3 + XS(rA,3,hloc));
        float iB = sigf(d0 + XS(rB,0,hloc));
        float fB = sigf(d1 + XS(rB,1,hloc));
        float gB = tanhf(d2 + XS(rB,2,hloc));
        float oB = sigf(d3 + XS(rB,3,hloc));
        cA = fA*cA + iA*gA;  cB = fB*cB + iB*gB;
        float hAo = oA*tanhf(cA), hBo = oB*tanhf(cB);

        __syncthreads();
        ST(0,rA,hloc)=hAo; ST(0,rB,hloc)=hBo;
        ST(1,rA,hloc)=iA;  ST(1,rB,hloc)=iB;
        ST(2,rA,hloc)=fA;  ST(2,rB,hloc)=fB;
        ST(3,rA,hloc)=gA;  ST(3,rB,hloc)=gB;
        ST(4,rA,hloc)=oA;  ST(4,rB,hloc)=oB;
        __syncthreads();

        // h: 128 float4 slots (16B-aligned targets). gates: 1024 float2 slots
        // (d_out gate sections are only 8B-aligned: OFF_IG*4 == 8 mod 16).
        for (int l=tid;l<1152;l+=256){
            if (l < 128){
                int r = l>>3, q4 = (l&7)<<2;
                float4 v = *(const float4*)&ST(0,r,q4);
                *(float4*)(hnx + (size_t)(b0+r)*HHD + hbase + q4) = v;
                *(float4*)(outb + ((size_t)(b0+r)*TT + t)*HHD + hbase + q4) = v;
            } else {
                int m = l - 128;
                int a = m >> 8;            // 0..3
                int r = (m >> 4) & 15;
                int q2 = (m & 15) << 1;
                float2 v = *(const float2*)&ST(a+1,r,q2);
                size_t base = ((size_t)(b0+r)*TT + t)*HHD + hbase + q2;
                float* gp = (a==0) ? gp1 : (a==1) ? gp2 : (a==2) ? gp3 : gp4;
                *(float2*)(gp + base) = v;
            }
        }

        if (t==TT-1){
            dout[OFF_HT + (size_t)bA*HHD + h] = hAo;
            dout[OFF_HT + (size_t)bB*HHD + h] = hBo;
            dout[OFF_CT + (size_t)bA*HHD + h] = cA;
            dout[OFF_CT + (size_t)bB*HHD + h] = cB;
        }

        __threadfence();
        __syncthreads();
        if (tid==0){
            unsigned v = atomicAdd(&g_arrive, 1u);
            if (v==127u){
                g_arrive = 0u;
                __threadfence();
                atomicExch(&g_release, (unsigned)(t+1));
            } else {
                while (*(volatile unsigned*)&g_release < (unsigned)(t+1)) { __nanosleep(64); }
            }
        }
        __syncthreads();
        __threadfence();
    }
#undef XS
#undef ST
}

__global__ __launch_bounds__(256)
void head_kernel(const float* __restrict__ Wa, const float* __restrict__ ba,
                 const float* __restrict__ Wc, const float* __restrict__ bc,
                 float* __restrict__ dout)
{
    __shared__ __align__(16) float xsr[16][516];
    const int tid = threadIdx.x;
    const size_t m0 = (size_t)blockIdx.x * 16;
    for (int l=tid;l<2048;l+=256){
        int r=l>>7, c4=(l&127)<<2;
        *(float4*)&xsr[r][c4] = *(const float4*)(g_enc1 + (m0+r)*HHD + c4);
    }
    __syncthreads();
    for (int o=tid;o<16*19;o+=256){
        int r=o/19, n=o-r*19;
        const float* wrow = (n<18) ? (Wa + (size_t)n*HHD) : Wc;
        float acc=0.f;
#pragma unroll 4
        for (int k=0;k<HHD;k+=4){
            float4 w = __ldg((const float4*)(wrow+k));
            float4 x = *(const float4*)&xsr[r][k];
            acc += x.x*w.x + x.y*w.y + x.z*w.z + x.w*w.w;
        }
        size_t m = m0 + r;
        if (n<18) dout[OFF_LOGITS + m*AA + n] = acc + ba[n];
        else      dout[OFF_VALUES + m] = acc + bc[0];
    }
}

__global__ __launch_bounds__(256)
void loss_partial()
{
    float s1=0.f, s2=0.f;
    const size_t n = (size_t)MM*HHD;
    for (size_t i=(size_t)blockIdx.x*256+threadIdx.x; i<n; i+=(size_t)LOSS_BLOCKS*256){
        float x = g_enc1[i];
        s1 += x*x;
        unsigned t = ((unsigned)(i>>9)) & 511u;
        if (t != 511u){ float d = g_enc1[i+512] - x; s2 += d*d; }
    }
    __shared__ double r1[256], r2[256];
    r1[threadIdx.x]=(double)s1; r2[threadIdx.x]=(double)s2;
    __syncthreads();
    for (int s=128;s>0;s>>=1){
        if (threadIdx.x<s){ r1[threadIdx.x]+=r1[threadIdx.x+s]; r2[threadIdx.x]+=r2[threadIdx.x+s]; }
        __syncthreads();
    }
    if (threadIdx.x==0){ g_part[0][blockIdx.x]=r1[0]; g_part[1][blockIdx.x]=r2[0]; }
}

__global__ void loss_final(float* __restrict__ dout)
{
    __shared__ double r1[256], r2[256];
    double s1=0.0, s2=0.0;
    for (int i=threadIdx.x;i<LOSS_BLOCKS;i+=256){ s1+=g_part[0][i]; s2+=g_part[1][i]; }
    r1[threadIdx.x]=s1; r2[threadIdx.x]=s2;
    __syncthreads();
    for (int s=128;s>0;s>>=1){
        if (threadIdx.x<s){ r1[threadIdx.x]+=r1[threadIdx.x+s]; r2[threadIdx.x]+=r2[threadIdx.x+s]; }
        __syncthreads();
    }
    if (threadIdx.x==0){
        dout[OFF_AR]  = (float)(r1[0] * (0.01 / ((double)MM * HHD)));
        dout[OFF_TAR] = (float)(r2[0] * (0.01 / ((double)BB * (TT-1) * HHD)));
    }
}

extern "C" void kernel_launch(void* const* d_in, const int* in_sizes, int n_in,
                              void* d_out, int out_size)
{
    const float* obs  = (const float*)d_in[0];
    const float* hxs  = (const float*)d_in[1];
    const float* cxs  = (const float*)d_in[2];
    const float* W1   = (const float*)d_in[3];
    const float* b1   = (const float*)d_in[4];
    const float* W2   = (const float*)d_in[5];
    const float* b2   = (const float*)d_in[6];
    const float* W_ih = (const float*)d_in[7];
    const float* W_hh = (const float*)d_in[8];
    const float* b_ih = (const float*)d_in[9];
    const float* b_hh = (const float*)d_in[10];
    const float* Wa   = (const float*)d_in[11];
    const float* ba   = (const float*)d_in[12];
    const float* Wc   = (const float*)d_in[13];
    const float* bc   = (const float*)d_in[14];
    float* dout = (float*)d_out;

    float* enc1; cudaGetSymbolAddress((void**)&enc1, g_enc1);
    float* enc2; cudaGetSymbolAddress((void**)&enc2, g_enc2);
    float* xg;   cudaGetSymbolAddress((void**)&xg,   g_xg);

    // enc1 = silu(obs @ W1^T + b1)   [65536 x 512, K=128]
    gemm_nt<1><<<dim3(ENC/128, MM/128), 256>>>(obs, W1, b1, nullptr, enc1, 128, ENC);
    // enc2 = silu(enc1 @ W2^T + b2)  [65536 x 512, K=512]
    gemm_nt<1><<<dim3(ENC/128, MM/128), 256>>>(enc1, W2, b2, nullptr, enc2, ENC, ENC);
    // xg = enc2 @ W_ih^T + b_ih + b_hh   [65536 x 2048, K=512]
    gemm_nt<0><<<dim3(G4/128, MM/128), 256>>>(enc2, W_ih, b_ih, b_hh, xg, ENC, G4);

    init_kernel<<<64, 256>>>(hxs);
    lstm_kernel<<<128, 256>>>(W_hh, cxs, dout);
    head_kernel<<<MM/16, 256>>>(Wa, ba, Wc, bc, dout);
    loss_partial<<<LOSS_BLOCKS, 256>>>();
    loss_final<<<1, 256>>>(dout);
}